// round 1
// baseline (speedup 1.0000x reference)
#include <cuda_runtime.h>
#include <cuda_bf16.h>

// Problem constants
#define B_   4
#define T_   2048
#define C_   1024
#define H_   16
#define DH_  64
#define M_   (B_ * T_)          // 8192
#define N_QKV (3 * C_)          // 3072

// Scratch (allocation-free rule: device globals)
__device__ float g_q[B_ * H_ * T_ * DH_];
__device__ float g_k[B_ * H_ * T_ * DH_];
__device__ float g_v[B_ * H_ * T_ * DH_];
__device__ float g_y[M_ * C_];

// ---------------------------------------------------------------------------
// Kernel 1: QKV GEMM (M=8192, N=3072, K=1024) with fused scatter to
// [B,H,T,Dh] layout. Q gets the 1/sqrt(Dh) scale folded in.
// 128x128 block tile, BK=16, 256 threads, 8x8 per thread.
// ---------------------------------------------------------------------------
__global__ __launch_bounds__(256) void qkv_gemm_kernel(
    const float* __restrict__ A,   // x [8192,1024]
    const float* __restrict__ Bm)  // w_qkv [1024,3072]
{
    const int K = C_;
    const int N = N_QKV;
    __shared__ float As[16][128];
    __shared__ float Bs[16][128];

    int tid = threadIdx.x;
    int m0 = blockIdx.y * 128;
    int n0 = blockIdx.x * 128;
    int tx = tid & 15, ty = tid >> 4;

    int arow = tid >> 1;
    int acol = (tid & 1) * 8;
    int brow = tid >> 4;           // 0..15
    int bcol = (tid & 15) * 8;     // 0..120

    float acc[8][8];
#pragma unroll
    for (int i = 0; i < 8; i++)
#pragma unroll
        for (int j = 0; j < 8; j++) acc[i][j] = 0.f;

    const float* Abase = A + (size_t)(m0 + arow) * K + acol;

    for (int kt = 0; kt < K; kt += 16) {
        float4 a0 = *(const float4*)(Abase + kt);
        float4 a1 = *(const float4*)(Abase + kt + 4);
        As[acol + 0][arow] = a0.x; As[acol + 1][arow] = a0.y;
        As[acol + 2][arow] = a0.z; As[acol + 3][arow] = a0.w;
        As[acol + 4][arow] = a1.x; As[acol + 5][arow] = a1.y;
        As[acol + 6][arow] = a1.z; As[acol + 7][arow] = a1.w;

        const float* bp = Bm + (size_t)(kt + brow) * N + n0 + bcol;
        *(float4*)&Bs[brow][bcol]     = *(const float4*)(bp);
        *(float4*)&Bs[brow][bcol + 4] = *(const float4*)(bp + 4);
        __syncthreads();

#pragma unroll
        for (int k = 0; k < 16; k++) {
            float4 xa0 = *(float4*)&As[k][ty * 8];
            float4 xa1 = *(float4*)&As[k][ty * 8 + 4];
            float4 xb0 = *(float4*)&Bs[k][tx * 8];
            float4 xb1 = *(float4*)&Bs[k][tx * 8 + 4];
            float a[8] = {xa0.x, xa0.y, xa0.z, xa0.w, xa1.x, xa1.y, xa1.z, xa1.w};
            float b[8] = {xb0.x, xb0.y, xb0.z, xb0.w, xb1.x, xb1.y, xb1.z, xb1.w};
#pragma unroll
            for (int i = 0; i < 8; i++)
#pragma unroll
                for (int j = 0; j < 8; j++) acc[i][j] = fmaf(a[i], b[j], acc[i][j]);
        }
        __syncthreads();
    }

    // scatter: n = which*1024 + h*64 + d  ->  q/k/v[((b*H+h)*T + t)*Dh + d]
    int which = n0 >> 10;   // constant per block (1024 % 128 == 0)
    float* dst = (which == 0) ? g_q : (which == 1) ? g_k : g_v;
    float scale = (which == 0) ? 0.125f : 1.0f;   // 1/sqrt(64)

#pragma unroll
    for (int i = 0; i < 8; i++) {
        int m = m0 + ty * 8 + i;
        int b = m >> 11;          // /2048
        int t = m & 2047;
#pragma unroll
        for (int j = 0; j < 8; j++) {
            int n = n0 + tx * 8 + j;
            int rem = n & 1023;
            int h = rem >> 6;
            int d = rem & 63;
            dst[(size_t)(((b << 4) + h) * T_ + t) * DH_ + d] = acc[i][j] * scale;
        }
    }
}

// ---------------------------------------------------------------------------
// Kernel 2: causal flash attention, fp32.
// Block: one (b,h) and one 64-row Q tile. 256 threads (16x16), each thread
// owns a 4x4 micro-tile of S/P and of O (rows ty*4+i, cols tx*4+j).
// K is staged d-major (Kt[d][c]) so the S-compute reads are LDS.128
// conflict-free. Online softmax with 16-lane shfl reductions.
// ---------------------------------------------------------------------------
#define AP 68   // smem row pad (floats); multiple of 4 keeps float4 alignment

__global__ __launch_bounds__(256) void attn_kernel(float* __restrict__ gy)
{
    extern __shared__ float sm[];
    float* Qs = sm;                 // [64][AP]  row-major (r, d)
    float* Kt = Qs + 64 * AP;       // [64][AP]  d-major   (d, c)
    float* Vs = Kt + 64 * AP;       // [64][AP]  row-major (c, d)
    float* Ps = Vs + 64 * AP;       // [64][AP]  (r, c)

    int qt = blockIdx.x;            // 0..31
    int bh = blockIdx.y;            // 0..63
    int b  = bh >> 4;
    int h  = bh & 15;

    int tid = threadIdx.x;
    int tx = tid & 15, ty = tid >> 4;

    const float* qbase = g_q + (size_t)bh * T_ * DH_;
    const float* kbase = g_k + (size_t)bh * T_ * DH_;
    const float* vbase = g_v + (size_t)bh * T_ * DH_;

    // load Q tile (each thread: row tid/4, 4 float4 covering d 0..63)
    {
        int r = tid >> 2;
        int c = (tid & 3) * 16;
        const float4* src = (const float4*)(qbase + (size_t)(qt * 64 + r) * DH_ + c);
        float4* dstq = (float4*)&Qs[r * AP + c];
#pragma unroll
        for (int u = 0; u < 4; u++) dstq[u] = src[u];
    }

    float O[4][4];
#pragma unroll
    for (int i = 0; i < 4; i++)
#pragma unroll
        for (int j = 0; j < 4; j++) O[i][j] = 0.f;
    float mrow[4], lrow[4];
#pragma unroll
    for (int i = 0; i < 4; i++) { mrow[i] = -1e30f; lrow[i] = 0.f; }

    for (int kt = 0; kt <= qt; kt++) {
        __syncthreads();  // protect Kt/Vs/Ps from previous iter consumers
        // load K (transposed to d-major) and V tiles
        {
            int r = tid >> 2;            // c index 0..63
            int c0 = (tid & 3) * 16;     // d base
            const float* ks = kbase + (size_t)(kt * 64 + r) * DH_ + c0;
            const float* vs = vbase + (size_t)(kt * 64 + r) * DH_ + c0;
            float kreg[16];
#pragma unroll
            for (int u = 0; u < 4; u++) *(float4*)&kreg[u * 4] = *(const float4*)(ks + u * 4);
#pragma unroll
            for (int u = 0; u < 16; u++) Kt[(c0 + u) * AP + r] = kreg[u];
            float4* dv = (float4*)&Vs[r * AP + c0];
#pragma unroll
            for (int u = 0; u < 4; u++) dv[u] = *(const float4*)(vs + u * 4);
        }
        __syncthreads();

        // S = Q @ K^T  (thread: rows ty*4+i, cols tx*4+j)
        float S[4][4];
#pragma unroll
        for (int i = 0; i < 4; i++)
#pragma unroll
            for (int j = 0; j < 4; j++) S[i][j] = 0.f;

#pragma unroll
        for (int d0 = 0; d0 < 64; d0 += 4) {
            float q4[4][4];
#pragma unroll
            for (int i = 0; i < 4; i++)
                *(float4*)q4[i] = *(float4*)&Qs[(ty * 4 + i) * AP + d0];
#pragma unroll
            for (int dd = 0; dd < 4; dd++) {
                float4 kv = *(float4*)&Kt[(d0 + dd) * AP + tx * 4];
#pragma unroll
                for (int i = 0; i < 4; i++) {
                    float qv = q4[i][dd];
                    S[i][0] = fmaf(qv, kv.x, S[i][0]);
                    S[i][1] = fmaf(qv, kv.y, S[i][1]);
                    S[i][2] = fmaf(qv, kv.z, S[i][2]);
                    S[i][3] = fmaf(qv, kv.w, S[i][3]);
                }
            }
        }

        // causal mask (only on the diagonal tile)
        if (kt == qt) {
#pragma unroll
            for (int i = 0; i < 4; i++)
#pragma unroll
                for (int j = 0; j < 4; j++)
                    if (tx * 4 + j > ty * 4 + i) S[i][j] = -1e30f;
        }

        // online softmax update
#pragma unroll
        for (int i = 0; i < 4; i++) {
            float mx = fmaxf(fmaxf(S[i][0], S[i][1]), fmaxf(S[i][2], S[i][3]));
#pragma unroll
            for (int off = 1; off < 16; off <<= 1)
                mx = fmaxf(mx, __shfl_xor_sync(0xffffffffu, mx, off));
            float mn = fmaxf(mrow[i], mx);
            float alpha = __expf(mrow[i] - mn);
            float ssum = 0.f;
#pragma unroll
            for (int j = 0; j < 4; j++) {
                S[i][j] = __expf(S[i][j] - mn);
                ssum += S[i][j];
            }
#pragma unroll
            for (int off = 1; off < 16; off <<= 1)
                ssum += __shfl_xor_sync(0xffffffffu, ssum, off);
            lrow[i] = lrow[i] * alpha + ssum;
            mrow[i] = mn;
#pragma unroll
            for (int j = 0; j < 4; j++) O[i][j] *= alpha;
        }

        // stage P to smem
#pragma unroll
        for (int i = 0; i < 4; i++)
            *(float4*)&Ps[(ty * 4 + i) * AP + tx * 4] = *(float4*)S[i];
        __syncthreads();

        // O += P @ V
#pragma unroll
        for (int c0 = 0; c0 < 64; c0 += 4) {
            float p4[4][4];
#pragma unroll
            for (int i = 0; i < 4; i++)
                *(float4*)p4[i] = *(float4*)&Ps[(ty * 4 + i) * AP + c0];
#pragma unroll
            for (int cc = 0; cc < 4; cc++) {
                float4 v4 = *(float4*)&Vs[(c0 + cc) * AP + tx * 4];
#pragma unroll
                for (int i = 0; i < 4; i++) {
                    float pe = p4[i][cc];
                    O[i][0] = fmaf(pe, v4.x, O[i][0]);
                    O[i][1] = fmaf(pe, v4.y, O[i][1]);
                    O[i][2] = fmaf(pe, v4.z, O[i][2]);
                    O[i][3] = fmaf(pe, v4.w, O[i][3]);
                }
            }
        }
    }

    // epilogue: y[b][t][h*64+d] = O / l
#pragma unroll
    for (int i = 0; i < 4; i++) {
        int r = ty * 4 + i;
        int t = qt * 64 + r;
        float inv = 1.f / lrow[i];
        float4 o = make_float4(O[i][0] * inv, O[i][1] * inv, O[i][2] * inv, O[i][3] * inv);
        *(float4*)&gy[(size_t)(b * T_ + t) * C_ + h * DH_ + tx * 4] = o;
    }
}

// ---------------------------------------------------------------------------
// Kernel 3: output projection GEMM (M=8192, N=1024, K=1024), plain store.
// ---------------------------------------------------------------------------
__global__ __launch_bounds__(256) void proj_gemm_kernel(
    const float* __restrict__ Bm,   // w_proj [1024,1024]
    float* __restrict__ Cout)
{
    const int K = C_;
    const int N = C_;
    __shared__ float As[16][128];
    __shared__ float Bs[16][128];

    int tid = threadIdx.x;
    int m0 = blockIdx.y * 128;
    int n0 = blockIdx.x * 128;
    int tx = tid & 15, ty = tid >> 4;

    int arow = tid >> 1;
    int acol = (tid & 1) * 8;
    int brow = tid >> 4;
    int bcol = (tid & 15) * 8;

    float acc[8][8];
#pragma unroll
    for (int i = 0; i < 8; i++)
#pragma unroll
        for (int j = 0; j < 8; j++) acc[i][j] = 0.f;

    const float* Abase = g_y + (size_t)(m0 + arow) * K + acol;

    for (int kt = 0; kt < K; kt += 16) {
        float4 a0 = *(const float4*)(Abase + kt);
        float4 a1 = *(const float4*)(Abase + kt + 4);
        As[acol + 0][arow] = a0.x; As[acol + 1][arow] = a0.y;
        As[acol + 2][arow] = a0.z; As[acol + 3][arow] = a0.w;
        As[acol + 4][arow] = a1.x; As[acol + 5][arow] = a1.y;
        As[acol + 6][arow] = a1.z; As[acol + 7][arow] = a1.w;

        const float* bp = Bm + (size_t)(kt + brow) * N + n0 + bcol;
        *(float4*)&Bs[brow][bcol]     = *(const float4*)(bp);
        *(float4*)&Bs[brow][bcol + 4] = *(const float4*)(bp + 4);
        __syncthreads();

#pragma unroll
        for (int k = 0; k < 16; k++) {
            float4 xa0 = *(float4*)&As[k][ty * 8];
            float4 xa1 = *(float4*)&As[k][ty * 8 + 4];
            float4 xb0 = *(float4*)&Bs[k][tx * 8];
            float4 xb1 = *(float4*)&Bs[k][tx * 8 + 4];
            float a[8] = {xa0.x, xa0.y, xa0.z, xa0.w, xa1.x, xa1.y, xa1.z, xa1.w};
            float b[8] = {xb0.x, xb0.y, xb0.z, xb0.w, xb1.x, xb1.y, xb1.z, xb1.w};
#pragma unroll
            for (int i = 0; i < 8; i++)
#pragma unroll
                for (int j = 0; j < 8; j++) acc[i][j] = fmaf(a[i], b[j], acc[i][j]);
        }
        __syncthreads();
    }

#pragma unroll
    for (int i = 0; i < 8; i++) {
        float* cp = Cout + (size_t)(m0 + ty * 8 + i) * N + n0 + tx * 8;
        *(float4*)(cp)     = make_float4(acc[i][0], acc[i][1], acc[i][2], acc[i][3]);
        *(float4*)(cp + 4) = make_float4(acc[i][4], acc[i][5], acc[i][6], acc[i][7]);
    }
}

// ---------------------------------------------------------------------------
extern "C" void kernel_launch(void* const* d_in, const int* in_sizes, int n_in,
                              void* d_out, int out_size)
{
    const float* x      = (const float*)d_in[0];
    const float* w_qkv  = (const float*)d_in[1];
    const float* w_proj = (const float*)d_in[2];
    float* out = (float*)d_out;

    (void)in_sizes; (void)n_in; (void)out_size;

    // 1) QKV projection with fused head-scatter (+ q scale)
    qkv_gemm_kernel<<<dim3(N_QKV / 128, M_ / 128), 256>>>(x, w_qkv);

    // 2) causal flash attention
    const int attn_smem = 4 * 64 * AP * (int)sizeof(float);   // 69632 B
    cudaFuncSetAttribute(attn_kernel, cudaFuncAttributeMaxDynamicSharedMemorySize, attn_smem);
    float* gy_ptr = nullptr;
    cudaGetSymbolAddress((void**)&gy_ptr, g_y);
    attn_kernel<<<dim3(T_ / 64, B_ * H_), 256, attn_smem>>>(gy_ptr);

    // 3) output projection
    proj_gemm_kernel<<<dim3(C_ / 128, M_ / 128), 256>>>(w_proj, out);
}

// round 3
// speedup vs baseline: 1.6992x; 1.6992x over previous
#include <cuda_runtime.h>
#include <cuda_bf16.h>
#include <cstdint>

// Problem constants
#define B_   4
#define T_   2048
#define C_   1024
#define H_   16
#define DH_  64
#define M_   (B_ * T_)          // 8192
#define N_QKV (3 * C_)          // 3072
#define K_   1024

// ---------------------------------------------------------------------------
// Device-global scratch (allocation-free rule)
// ---------------------------------------------------------------------------
__device__ float g_q[B_ * H_ * T_ * DH_];
__device__ float g_k[B_ * H_ * T_ * DH_];
__device__ float g_v[B_ * H_ * T_ * DH_];
__device__ __nv_bfloat16 g_xh[M_ * K_];
__device__ __nv_bfloat16 g_xl[M_ * K_];
__device__ __nv_bfloat16 g_yh[M_ * C_];
__device__ __nv_bfloat16 g_yl[M_ * C_];
__device__ __nv_bfloat16 g_wqkvTh[N_QKV * K_];   // [N][K]
__device__ __nv_bfloat16 g_wqkvTl[N_QKV * K_];
__device__ __nv_bfloat16 g_wprojTh[C_ * K_];
__device__ __nv_bfloat16 g_wprojTl[C_ * K_];

#define SMEM_SWIZZLE_128B(o) ((o) ^ (((o) >> 3) & 0x70))

__device__ __forceinline__ uint32_t smem_to_u32(const void* p) {
    uint32_t a;
    asm("{ .reg .u64 t; cvta.to.shared.u64 t, %1; cvt.u32.u64 %0, t; }" : "=r"(a) : "l"(p));
    return a;
}
__device__ __forceinline__ void cp16(uint32_t saddr, const void* g) {
    asm volatile("cp.async.cg.shared.global [%0], [%1], 16;" :: "r"(saddr), "l"(g));
}
__device__ __forceinline__ void cp_commit() {
    asm volatile("cp.async.commit_group;" ::: "memory");
}
__device__ __forceinline__ void ldsm_x4(uint32_t* r, uint32_t addr) {
    asm volatile("ldmatrix.sync.aligned.m8n8.x4.shared.b16 {%0,%1,%2,%3}, [%4];"
        : "=r"(r[0]), "=r"(r[1]), "=r"(r[2]), "=r"(r[3]) : "r"(addr));
}
__device__ __forceinline__ void ldsm_x2(uint32_t* r, uint32_t addr) {
    asm volatile("ldmatrix.sync.aligned.m8n8.x2.shared.b16 {%0,%1}, [%2];"
        : "=r"(r[0]), "=r"(r[1]) : "r"(addr));
}
__device__ __forceinline__ void mma_bf16(float* c, const uint32_t* a, const uint32_t* b) {
    asm volatile("mma.sync.aligned.m16n8k16.row.col.f32.bf16.bf16.f32 "
        "{%0,%1,%2,%3}, {%4,%5,%6,%7}, {%8,%9}, {%0,%1,%2,%3};"
        : "+f"(c[0]), "+f"(c[1]), "+f"(c[2]), "+f"(c[3])
        : "r"(a[0]), "r"(a[1]), "r"(a[2]), "r"(a[3]), "r"(b[0]), "r"(b[1]));
}

// ---------------------------------------------------------------------------
// Prep kernel 1: split x (fp32) into bf16 hi/lo
// ---------------------------------------------------------------------------
__global__ __launch_bounds__(256) void convert_x_kernel(const float* __restrict__ x)
{
    int idx = (blockIdx.x * 256 + threadIdx.x) * 4;
    float4 v = *(const float4*)(x + idx);
    __nv_bfloat16 h[4], l[4];
    float vv[4] = {v.x, v.y, v.z, v.w};
#pragma unroll
    for (int i = 0; i < 4; i++) {
        h[i] = __float2bfloat16(vv[i]);
        l[i] = __float2bfloat16(vv[i] - __bfloat162float(h[i]));
    }
    *(uint2*)(g_xh + idx) = *(uint2*)h;
    *(uint2*)(g_xl + idx) = *(uint2*)l;
}

// ---------------------------------------------------------------------------
// Prep kernel 2: transpose W [K,N] -> WT hi/lo [N,K] bf16
// ---------------------------------------------------------------------------
__global__ __launch_bounds__(256) void transpose_w_kernel(
    const float* __restrict__ W, __nv_bfloat16* __restrict__ WTh,
    __nv_bfloat16* __restrict__ WTl, int N)
{
    __shared__ float t[32][33];
    int n0 = blockIdx.x * 32, k0 = blockIdx.y * 32;
    int tx = threadIdx.x, ty = threadIdx.y;
#pragma unroll
    for (int i = 0; i < 4; i++)
        t[ty + i * 8][tx] = W[(size_t)(k0 + ty + i * 8) * N + n0 + tx];
    __syncthreads();
#pragma unroll
    for (int i = 0; i < 4; i++) {
        int n = n0 + ty + i * 8;
        int k = k0 + tx;
        float v = t[tx][ty + i * 8];
        __nv_bfloat16 h = __float2bfloat16(v);
        __nv_bfloat16 l = __float2bfloat16(v - __bfloat162float(h));
        WTh[(size_t)n * K_ + k] = h;
        WTl[(size_t)n * K_ + k] = l;
    }
}

// ---------------------------------------------------------------------------
// Tensor-core GEMM via mma.sync bf16 (3-term hi/lo split).
// C[M,N] = A[M,K] @ B[N,K]^T.  128x128 CTA tile, BK=64, 8 warps (2x4),
// warp tile 64x32, cp.async double-buffered smem, SW128-swizzled ldmatrix.
// mode 0: scatter into g_q/g_k/g_v with q-scale; mode 1: row store to out.
// ---------------------------------------------------------------------------
#define STAGE_BYTES 65536    // Ah(16K) Al(16K) Bh(16K) Bl(16K)
#define SM_GEMM_TOTAL (2 * STAGE_BYTES)

__global__ __launch_bounds__(256) void mma_gemm_kernel(
    const __nv_bfloat16* __restrict__ Ah, const __nv_bfloat16* __restrict__ Al,
    const __nv_bfloat16* __restrict__ Bh, const __nv_bfloat16* __restrict__ Bl,
    float* __restrict__ out, int mode)
{
    extern __shared__ char smem[];
    uint32_t sbase = smem_to_u32(smem);

    int tid = threadIdx.x;
    int wid = tid >> 5;
    int lane = tid & 31;
    int wm = wid >> 2;          // 0..1 (m)
    int wn = wid & 3;           // 0..3 (n)

    int m0 = blockIdx.y * 128;
    int n0 = blockIdx.x * 128;

    float acc[4][4][4];
#pragma unroll
    for (int i = 0; i < 4; i++)
#pragma unroll
        for (int j = 0; j < 4; j++)
#pragma unroll
            for (int c = 0; c < 4; c++) acc[i][j][c] = 0.f;

    // ---- async load of chunk kt into stage s ----
    auto load_chunk = [&](int kt, int s) {
        uint32_t st = sbase + s * STAGE_BYTES;
#pragma unroll
        for (int p = 0; p < 4; p++) {
            int idx = tid + p * 256;         // 0..1023
            int row = idx >> 3;
            int ch  = idx & 7;
            uint32_t so = SMEM_SWIZZLE_128B(row * 128 + ch * 16);
            size_t ka = (size_t)(m0 + row) * K_ + kt * 64 + ch * 8;
            size_t kb = (size_t)(n0 + row) * K_ + kt * 64 + ch * 8;
            cp16(st + so,         Ah + ka);
            cp16(st + 16384 + so, Al + ka);
            cp16(st + 32768 + so, Bh + kb);
            cp16(st + 49152 + so, Bl + kb);
        }
        cp_commit();
    };

    load_chunk(0, 0);

    // precomputed per-thread ldmatrix row/col components
    int a_row = lane & 15;            // row within m16 tile
    int a_cb  = (lane >> 4) << 4;     // +16B for lanes 16-31
    int b_row = lane & 7;             // row within n8 tile
    int b_cb  = ((lane >> 3) & 1) << 4;

    for (int kt = 0; kt < 16; kt++) {
        int s = kt & 1;
        if (kt + 1 < 16) load_chunk(kt + 1, (kt + 1) & 1);
        if (kt + 1 < 16)
            asm volatile("cp.async.wait_group 1;" ::: "memory");
        else
            asm volatile("cp.async.wait_group 0;" ::: "memory");
        __syncthreads();

        uint32_t sAh = sbase + s * STAGE_BYTES;
        uint32_t sAl = sAh + 16384;
        uint32_t sBh = sAh + 32768;
        uint32_t sBl = sAh + 49152;

#pragma unroll
        for (int ks = 0; ks < 4; ks++) {
            int kB = ks * 32;
            uint32_t ah[4][4], al[4][4], bh[4][2], bl[4][2];
#pragma unroll
            for (int i = 0; i < 4; i++) {
                uint32_t off = SMEM_SWIZZLE_128B((wm * 64 + i * 16 + a_row) * 128 + kB + a_cb);
                ldsm_x4(ah[i], sAh + off);
                ldsm_x4(al[i], sAl + off);
            }
#pragma unroll
            for (int j = 0; j < 4; j++) {
                uint32_t off = SMEM_SWIZZLE_128B((wn * 32 + j * 8 + b_row) * 128 + kB + b_cb);
                ldsm_x2(bh[j], sBh + off);
                ldsm_x2(bl[j], sBl + off);
            }
#pragma unroll
            for (int i = 0; i < 4; i++)
#pragma unroll
                for (int j = 0; j < 4; j++) mma_bf16(acc[i][j], ah[i], bh[j]);
#pragma unroll
            for (int i = 0; i < 4; i++)
#pragma unroll
                for (int j = 0; j < 4; j++) mma_bf16(acc[i][j], ah[i], bl[j]);
#pragma unroll
            for (int i = 0; i < 4; i++)
#pragma unroll
                for (int j = 0; j < 4; j++) mma_bf16(acc[i][j], al[i], bh[j]);
        }
        __syncthreads();
    }

    // ---- epilogue ----
    int r4 = lane >> 2;
    int cp2 = (lane & 3) * 2;

    if (mode == 1) {
#pragma unroll
        for (int i = 0; i < 4; i++)
#pragma unroll
            for (int j = 0; j < 4; j++) {
                int n = n0 + wn * 32 + j * 8 + cp2;
#pragma unroll
                for (int rr = 0; rr < 2; rr++) {
                    int m = m0 + wm * 64 + i * 16 + r4 + rr * 8;
                    *(float2*)(out + (size_t)m * C_ + n) =
                        make_float2(acc[i][j][rr * 2], acc[i][j][rr * 2 + 1]);
                }
            }
    } else {
        int which = n0 >> 10;    // constant per CTA (128 | 1024)
        float* dst = (which == 0) ? g_q : (which == 1) ? g_k : g_v;
        float scale = (which == 0) ? 0.125f : 1.0f;
#pragma unroll
        for (int i = 0; i < 4; i++)
#pragma unroll
            for (int j = 0; j < 4; j++) {
                int n = n0 + wn * 32 + j * 8 + cp2;
                int h = (n & 1023) >> 6;
                int d = n & 63;
#pragma unroll
                for (int rr = 0; rr < 2; rr++) {
                    int m = m0 + wm * 64 + i * 16 + r4 + rr * 8;
                    int b = m >> 11;
                    int t = m & 2047;
                    *(float2*)(dst + (size_t)(((b << 4) + h) * T_ + t) * DH_ + d) =
                        make_float2(acc[i][j][rr * 2] * scale, acc[i][j][rr * 2 + 1] * scale);
                }
            }
    }
}

// ---------------------------------------------------------------------------
// Causal flash attention, fp32. Epilogue writes y as bf16 hi/lo.
// ---------------------------------------------------------------------------
#define AP 68

__global__ __launch_bounds__(256) void attn_kernel()
{
    extern __shared__ float sm[];
    float* Qs = sm;
    float* Kt = Qs + 64 * AP;
    float* Vs = Kt + 64 * AP;
    float* Ps = Vs + 64 * AP;

    int qt = blockIdx.x;
    int bh = blockIdx.y;
    int b  = bh >> 4;
    int h  = bh & 15;

    int tid = threadIdx.x;
    int tx = tid & 15, ty = tid >> 4;

    const float* qbase = g_q + (size_t)bh * T_ * DH_;
    const float* kbase = g_k + (size_t)bh * T_ * DH_;
    const float* vbase = g_v + (size_t)bh * T_ * DH_;

    {
        int r = tid >> 2;
        int c = (tid & 3) * 16;
        const float4* src = (const float4*)(qbase + (size_t)(qt * 64 + r) * DH_ + c);
        float4* dstq = (float4*)&Qs[r * AP + c];
#pragma unroll
        for (int u = 0; u < 4; u++) dstq[u] = src[u];
    }

    float O[4][4];
#pragma unroll
    for (int i = 0; i < 4; i++)
#pragma unroll
        for (int j = 0; j < 4; j++) O[i][j] = 0.f;
    float mrow[4], lrow[4];
#pragma unroll
    for (int i = 0; i < 4; i++) { mrow[i] = -1e30f; lrow[i] = 0.f; }

    for (int kt = 0; kt <= qt; kt++) {
        __syncthreads();
        {
            int r = tid >> 2;
            int c0 = (tid & 3) * 16;
            const float* ks = kbase + (size_t)(kt * 64 + r) * DH_ + c0;
            const float* vs = vbase + (size_t)(kt * 64 + r) * DH_ + c0;
            float kreg[16];
#pragma unroll
            for (int u = 0; u < 4; u++) *(float4*)&kreg[u * 4] = *(const float4*)(ks + u * 4);
#pragma unroll
            for (int u = 0; u < 16; u++) Kt[(c0 + u) * AP + r] = kreg[u];
            float4* dv = (float4*)&Vs[r * AP + c0];
#pragma unroll
            for (int u = 0; u < 4; u++) dv[u] = *(const float4*)(vs + u * 4);
        }
        __syncthreads();

        float S[4][4];
#pragma unroll
        for (int i = 0; i < 4; i++)
#pragma unroll
            for (int j = 0; j < 4; j++) S[i][j] = 0.f;

#pragma unroll
        for (int d0 = 0; d0 < 64; d0 += 4) {
            float q4[4][4];
#pragma unroll
            for (int i = 0; i < 4; i++)
                *(float4*)q4[i] = *(float4*)&Qs[(ty * 4 + i) * AP + d0];
#pragma unroll
            for (int dd = 0; dd < 4; dd++) {
                float4 kv = *(float4*)&Kt[(d0 + dd) * AP + tx * 4];
#pragma unroll
                for (int i = 0; i < 4; i++) {
                    float qv = q4[i][dd];
                    S[i][0] = fmaf(qv, kv.x, S[i][0]);
                    S[i][1] = fmaf(qv, kv.y, S[i][1]);
                    S[i][2] = fmaf(qv, kv.z, S[i][2]);
                    S[i][3] = fmaf(qv, kv.w, S[i][3]);
                }
            }
        }

        if (kt == qt) {
#pragma unroll
            for (int i = 0; i < 4; i++)
#pragma unroll
                for (int j = 0; j < 4; j++)
                    if (tx * 4 + j > ty * 4 + i) S[i][j] = -1e30f;
        }

#pragma unroll
        for (int i = 0; i < 4; i++) {
            float mx = fmaxf(fmaxf(S[i][0], S[i][1]), fmaxf(S[i][2], S[i][3]));
#pragma unroll
            for (int off = 1; off < 16; off <<= 1)
                mx = fmaxf(mx, __shfl_xor_sync(0xffffffffu, mx, off));
            float mn = fmaxf(mrow[i], mx);
            float alpha = __expf(mrow[i] - mn);
            float ssum = 0.f;
#pragma unroll
            for (int j = 0; j < 4; j++) {
                S[i][j] = __expf(S[i][j] - mn);
                ssum += S[i][j];
            }
#pragma unroll
            for (int off = 1; off < 16; off <<= 1)
                ssum += __shfl_xor_sync(0xffffffffu, ssum, off);
            lrow[i] = lrow[i] * alpha + ssum;
            mrow[i] = mn;
#pragma unroll
            for (int j = 0; j < 4; j++) O[i][j] *= alpha;
        }

#pragma unroll
        for (int i = 0; i < 4; i++)
            *(float4*)&Ps[(ty * 4 + i) * AP + tx * 4] = *(float4*)S[i];
        __syncthreads();

#pragma unroll
        for (int c0 = 0; c0 < 64; c0 += 4) {
            float p4[4][4];
#pragma unroll
            for (int i = 0; i < 4; i++)
                *(float4*)p4[i] = *(float4*)&Ps[(ty * 4 + i) * AP + c0];
#pragma unroll
            for (int cc = 0; cc < 4; cc++) {
                float4 v4 = *(float4*)&Vs[(c0 + cc) * AP + tx * 4];
#pragma unroll
                for (int i = 0; i < 4; i++) {
                    float pe = p4[i][cc];
                    O[i][0] = fmaf(pe, v4.x, O[i][0]);
                    O[i][1] = fmaf(pe, v4.y, O[i][1]);
                    O[i][2] = fmaf(pe, v4.z, O[i][2]);
                    O[i][3] = fmaf(pe, v4.w, O[i][3]);
                }
            }
        }
    }

#pragma unroll
    for (int i = 0; i < 4; i++) {
        int t = qt * 64 + ty * 4 + i;
        float inv = 1.f / lrow[i];
        size_t base = (size_t)(b * T_ + t) * C_ + h * DH_ + tx * 4;
        __nv_bfloat16 hv[4], lv[4];
#pragma unroll
        for (int j = 0; j < 4; j++) {
            float v = O[i][j] * inv;
            hv[j] = __float2bfloat16(v);
            lv[j] = __float2bfloat16(v - __bfloat162float(hv[j]));
        }
        *(uint2*)(g_yh + base) = *(uint2*)hv;
        *(uint2*)(g_yl + base) = *(uint2*)lv;
    }
}

// ---------------------------------------------------------------------------
extern "C" void kernel_launch(void* const* d_in, const int* in_sizes, int n_in,
                              void* d_out, int out_size)
{
    const float* x      = (const float*)d_in[0];
    const float* w_qkv  = (const float*)d_in[1];
    const float* w_proj = (const float*)d_in[2];
    float* out = (float*)d_out;
    (void)in_sizes; (void)n_in; (void)out_size;

    cudaFuncSetAttribute(mma_gemm_kernel,
                         cudaFuncAttributeMaxDynamicSharedMemorySize, SM_GEMM_TOTAL);
    cudaFuncSetAttribute(attn_kernel,
                         cudaFuncAttributeMaxDynamicSharedMemorySize, 4 * 64 * AP * (int)sizeof(float));

    __nv_bfloat16 *xh, *xl, *yh, *yl, *wqh, *wql, *wph, *wpl;
    cudaGetSymbolAddress((void**)&xh,  g_xh);
    cudaGetSymbolAddress((void**)&xl,  g_xl);
    cudaGetSymbolAddress((void**)&yh,  g_yh);
    cudaGetSymbolAddress((void**)&yl,  g_yl);
    cudaGetSymbolAddress((void**)&wqh, g_wqkvTh);
    cudaGetSymbolAddress((void**)&wql, g_wqkvTl);
    cudaGetSymbolAddress((void**)&wph, g_wprojTh);
    cudaGetSymbolAddress((void**)&wpl, g_wprojTl);

    // prep: split x, transpose+split weights
    convert_x_kernel<<<M_ * K_ / (256 * 4), 256>>>(x);
    transpose_w_kernel<<<dim3(N_QKV / 32, K_ / 32), dim3(32, 8)>>>(w_qkv, wqh, wql, N_QKV);
    transpose_w_kernel<<<dim3(C_ / 32, K_ / 32), dim3(32, 8)>>>(w_proj, wph, wpl, C_);

    // QKV GEMM (tensor cores) with fused scatter + q scale
    mma_gemm_kernel<<<dim3(N_QKV / 128, M_ / 128), 256, SM_GEMM_TOTAL>>>(
        xh, xl, wqh, wql, nullptr, 0);

    // causal flash attention (fp32), writes bf16 hi/lo y
    attn_kernel<<<dim3(T_ / 64, B_ * H_), 256, 4 * 64 * AP * (int)sizeof(float)>>>();

    // output projection GEMM (tensor cores)
    mma_gemm_kernel<<<dim3(C_ / 128, M_ / 128), 256, SM_GEMM_TOTAL>>>(
        yh, yl, wph, wpl, out, 1);
}

// round 4
// speedup vs baseline: 3.1471x; 1.8521x over previous
#include <cuda_runtime.h>
#include <cuda_bf16.h>
#include <cstdint>

// Problem constants
#define B_   4
#define T_   2048
#define C_   1024
#define H_   16
#define DH_  64
#define M_   (B_ * T_)          // 8192
#define N_QKV (3 * C_)          // 3072
#define K_   1024

// ---------------------------------------------------------------------------
// Device-global scratch (allocation-free rule)
// ---------------------------------------------------------------------------
__device__ __nv_bfloat16 g_qh[B_ * H_ * T_ * DH_];
__device__ __nv_bfloat16 g_ql[B_ * H_ * T_ * DH_];
__device__ __nv_bfloat16 g_kh[B_ * H_ * T_ * DH_];
__device__ __nv_bfloat16 g_kl[B_ * H_ * T_ * DH_];
__device__ __nv_bfloat16 g_vh[B_ * H_ * T_ * DH_];
__device__ __nv_bfloat16 g_vl[B_ * H_ * T_ * DH_];
__device__ __nv_bfloat16 g_xh[M_ * K_];
__device__ __nv_bfloat16 g_xl[M_ * K_];
__device__ __nv_bfloat16 g_yh[M_ * C_];
__device__ __nv_bfloat16 g_yl[M_ * C_];
__device__ __nv_bfloat16 g_wqkvTh[N_QKV * K_];   // [N][K]
__device__ __nv_bfloat16 g_wqkvTl[N_QKV * K_];
__device__ __nv_bfloat16 g_wprojTh[C_ * K_];
__device__ __nv_bfloat16 g_wprojTl[C_ * K_];

#define SMEM_SWIZZLE_128B(o) ((o) ^ (((o) >> 3) & 0x70))

__device__ __forceinline__ uint32_t smem_to_u32(const void* p) {
    uint32_t a;
    asm("{ .reg .u64 t; cvta.to.shared.u64 t, %1; cvt.u32.u64 %0, t; }" : "=r"(a) : "l"(p));
    return a;
}
__device__ __forceinline__ void cp16(uint32_t saddr, const void* g) {
    asm volatile("cp.async.cg.shared.global [%0], [%1], 16;" :: "r"(saddr), "l"(g));
}
__device__ __forceinline__ void cp_commit() {
    asm volatile("cp.async.commit_group;" ::: "memory");
}
__device__ __forceinline__ void ldsm_x4(uint32_t* r, uint32_t addr) {
    asm volatile("ldmatrix.sync.aligned.m8n8.x4.shared.b16 {%0,%1,%2,%3}, [%4];"
        : "=r"(r[0]), "=r"(r[1]), "=r"(r[2]), "=r"(r[3]) : "r"(addr));
}
__device__ __forceinline__ void ldsm_x2(uint32_t* r, uint32_t addr) {
    asm volatile("ldmatrix.sync.aligned.m8n8.x2.shared.b16 {%0,%1}, [%2];"
        : "=r"(r[0]), "=r"(r[1]) : "r"(addr));
}
__device__ __forceinline__ void ldsm_x2_trans(uint32_t* r, uint32_t addr) {
    asm volatile("ldmatrix.sync.aligned.m8n8.x2.trans.shared.b16 {%0,%1}, [%2];"
        : "=r"(r[0]), "=r"(r[1]) : "r"(addr));
}
__device__ __forceinline__ void mma_bf16(float* c, const uint32_t* a, const uint32_t* b) {
    asm volatile("mma.sync.aligned.m16n8k16.row.col.f32.bf16.bf16.f32 "
        "{%0,%1,%2,%3}, {%4,%5,%6,%7}, {%8,%9}, {%0,%1,%2,%3};"
        : "+f"(c[0]), "+f"(c[1]), "+f"(c[2]), "+f"(c[3])
        : "r"(a[0]), "r"(a[1]), "r"(a[2]), "r"(a[3]), "r"(b[0]), "r"(b[1]));
}
__device__ __forceinline__ uint32_t cvt_bf16x2(float hi, float lo) {
    uint32_t d;
    asm("cvt.rn.bf16x2.f32 %0, %1, %2;" : "=r"(d) : "f"(hi), "f"(lo));
    return d;
}
__device__ __forceinline__ uint32_t pack_bf16_rn(float a, float b) {  // lo=a, hi=b
    __nv_bfloat16 ha = __float2bfloat16(a), hb = __float2bfloat16(b);
    uint16_t ua, ub;
    memcpy(&ua, &ha, 2); memcpy(&ub, &hb, 2);
    return (uint32_t)ua | ((uint32_t)ub << 16);
}

// ---------------------------------------------------------------------------
// Prep: split x (fp32) into bf16 hi/lo
// ---------------------------------------------------------------------------
__global__ __launch_bounds__(256) void convert_x_kernel(const float* __restrict__ x)
{
    int idx = (blockIdx.x * 256 + threadIdx.x) * 4;
    float4 v = *(const float4*)(x + idx);
    __nv_bfloat16 h[4], l[4];
    float vv[4] = {v.x, v.y, v.z, v.w};
#pragma unroll
    for (int i = 0; i < 4; i++) {
        h[i] = __float2bfloat16(vv[i]);
        l[i] = __float2bfloat16(vv[i] - __bfloat162float(h[i]));
    }
    *(uint2*)(g_xh + idx) = *(uint2*)h;
    *(uint2*)(g_xl + idx) = *(uint2*)l;
}

// ---------------------------------------------------------------------------
// Prep: transpose W [K,N] -> WT hi/lo [N,K] bf16
// ---------------------------------------------------------------------------
__global__ __launch_bounds__(256) void transpose_w_kernel(
    const float* __restrict__ W, __nv_bfloat16* __restrict__ WTh,
    __nv_bfloat16* __restrict__ WTl, int N)
{
    __shared__ float t[32][33];
    int n0 = blockIdx.x * 32, k0 = blockIdx.y * 32;
    int tx = threadIdx.x, ty = threadIdx.y;
#pragma unroll
    for (int i = 0; i < 4; i++)
        t[ty + i * 8][tx] = W[(size_t)(k0 + ty + i * 8) * N + n0 + tx];
    __syncthreads();
#pragma unroll
    for (int i = 0; i < 4; i++) {
        int n = n0 + ty + i * 8;
        int k = k0 + tx;
        float v = t[tx][ty + i * 8];
        __nv_bfloat16 h = __float2bfloat16(v);
        __nv_bfloat16 l = __float2bfloat16(v - __bfloat162float(h));
        WTh[(size_t)n * K_ + k] = h;
        WTl[(size_t)n * K_ + k] = l;
    }
}

// ---------------------------------------------------------------------------
// Tensor-core GEMM (3-term hi/lo split). C[M,N] = A[M,K] @ B[N,K]^T.
// mode 0: split-scatter into g_{q,k,v}{h,l} with q-scale; mode 1: f32 store.
// ---------------------------------------------------------------------------
#define STAGE_BYTES 65536
#define SM_GEMM_TOTAL (2 * STAGE_BYTES)

__global__ __launch_bounds__(256) void mma_gemm_kernel(
    const __nv_bfloat16* __restrict__ Ah, const __nv_bfloat16* __restrict__ Al,
    const __nv_bfloat16* __restrict__ Bh, const __nv_bfloat16* __restrict__ Bl,
    float* __restrict__ out, int mode)
{
    extern __shared__ char smem[];
    uint32_t sbase = smem_to_u32(smem);

    int tid = threadIdx.x;
    int wid = tid >> 5;
    int lane = tid & 31;
    int wm = wid >> 2;
    int wn = wid & 3;

    int m0 = blockIdx.y * 128;
    int n0 = blockIdx.x * 128;

    float acc[4][4][4];
#pragma unroll
    for (int i = 0; i < 4; i++)
#pragma unroll
        for (int j = 0; j < 4; j++)
#pragma unroll
            for (int c = 0; c < 4; c++) acc[i][j][c] = 0.f;

    auto load_chunk = [&](int kt, int s) {
        uint32_t st = sbase + s * STAGE_BYTES;
#pragma unroll
        for (int p = 0; p < 4; p++) {
            int idx = tid + p * 256;
            int row = idx >> 3;
            int ch  = idx & 7;
            uint32_t so = SMEM_SWIZZLE_128B(row * 128 + ch * 16);
            size_t ka = (size_t)(m0 + row) * K_ + kt * 64 + ch * 8;
            size_t kb = (size_t)(n0 + row) * K_ + kt * 64 + ch * 8;
            cp16(st + so,         Ah + ka);
            cp16(st + 16384 + so, Al + ka);
            cp16(st + 32768 + so, Bh + kb);
            cp16(st + 49152 + so, Bl + kb);
        }
        cp_commit();
    };

    load_chunk(0, 0);

    int a_row = lane & 15;
    int a_cb  = (lane >> 4) << 4;
    int b_row = lane & 7;
    int b_cb  = ((lane >> 3) & 1) << 4;

    for (int kt = 0; kt < 16; kt++) {
        int s = kt & 1;
        if (kt + 1 < 16) load_chunk(kt + 1, (kt + 1) & 1);
        if (kt + 1 < 16)
            asm volatile("cp.async.wait_group 1;" ::: "memory");
        else
            asm volatile("cp.async.wait_group 0;" ::: "memory");
        __syncthreads();

        uint32_t sAh = sbase + s * STAGE_BYTES;
        uint32_t sAl = sAh + 16384;
        uint32_t sBh = sAh + 32768;
        uint32_t sBl = sAh + 49152;

#pragma unroll
        for (int ks = 0; ks < 4; ks++) {
            int kB = ks * 32;
            uint32_t ah[4][4], al[4][4], bh[4][2], bl[4][2];
#pragma unroll
            for (int i = 0; i < 4; i++) {
                uint32_t off = SMEM_SWIZZLE_128B((wm * 64 + i * 16 + a_row) * 128 + kB + a_cb);
                ldsm_x4(ah[i], sAh + off);
                ldsm_x4(al[i], sAl + off);
            }
#pragma unroll
            for (int j = 0; j < 4; j++) {
                uint32_t off = SMEM_SWIZZLE_128B((wn * 32 + j * 8 + b_row) * 128 + kB + b_cb);
                ldsm_x2(bh[j], sBh + off);
                ldsm_x2(bl[j], sBl + off);
            }
#pragma unroll
            for (int i = 0; i < 4; i++)
#pragma unroll
                for (int j = 0; j < 4; j++) mma_bf16(acc[i][j], ah[i], bh[j]);
#pragma unroll
            for (int i = 0; i < 4; i++)
#pragma unroll
                for (int j = 0; j < 4; j++) mma_bf16(acc[i][j], ah[i], bl[j]);
#pragma unroll
            for (int i = 0; i < 4; i++)
#pragma unroll
                for (int j = 0; j < 4; j++) mma_bf16(acc[i][j], al[i], bh[j]);
        }
        __syncthreads();
    }

    int r4 = lane >> 2;
    int cp2 = (lane & 3) * 2;

    if (mode == 1) {
#pragma unroll
        for (int i = 0; i < 4; i++)
#pragma unroll
            for (int j = 0; j < 4; j++) {
                int n = n0 + wn * 32 + j * 8 + cp2;
#pragma unroll
                for (int rr = 0; rr < 2; rr++) {
                    int m = m0 + wm * 64 + i * 16 + r4 + rr * 8;
                    *(float2*)(out + (size_t)m * C_ + n) =
                        make_float2(acc[i][j][rr * 2], acc[i][j][rr * 2 + 1]);
                }
            }
    } else {
        int which = n0 >> 10;
        __nv_bfloat16* dh = (which == 0) ? g_qh : (which == 1) ? g_kh : g_vh;
        __nv_bfloat16* dl = (which == 0) ? g_ql : (which == 1) ? g_kl : g_vl;
        float scale = (which == 0) ? 0.125f : 1.0f;
#pragma unroll
        for (int i = 0; i < 4; i++)
#pragma unroll
            for (int j = 0; j < 4; j++) {
                int n = n0 + wn * 32 + j * 8 + cp2;
                int h = (n & 1023) >> 6;
                int d = n & 63;
#pragma unroll
                for (int rr = 0; rr < 2; rr++) {
                    int m = m0 + wm * 64 + i * 16 + r4 + rr * 8;
                    int b = m >> 11;
                    int t = m & 2047;
                    size_t off = (size_t)(((b << 4) + h) * T_ + t) * DH_ + d;
                    float v0 = acc[i][j][rr * 2] * scale;
                    float v1 = acc[i][j][rr * 2 + 1] * scale;
                    __nv_bfloat16 h0 = __float2bfloat16(v0);
                    __nv_bfloat16 h1 = __float2bfloat16(v1);
                    float l0 = v0 - __bfloat162float(h0);
                    float l1 = v1 - __bfloat162float(h1);
                    uint16_t u0, u1;
                    memcpy(&u0, &h0, 2); memcpy(&u1, &h1, 2);
                    *(uint32_t*)(dh + off) = (uint32_t)u0 | ((uint32_t)u1 << 16);
                    *(uint32_t*)(dl + off) = cvt_bf16x2(l1, l0);
                }
            }
    }
}

// ---------------------------------------------------------------------------
// Tensor-core causal flash attention.
// CTA: 128 Q rows of one (b,h); 8 warps x 16 rows. K-tiles of 64 kv,
// cp.async double-buffered. S and PV both 3-term hi/lo HMMA.
// ---------------------------------------------------------------------------
#define AS_QH 0
#define AS_QL 16384
#define AS_KV 32768           // + stage*32768 : Kh|Kl|Vh|Vl each 8192
#define AS_TOTAL (32768 + 2 * 32768)   // 98304

__global__ __launch_bounds__(256) void attn_mma_kernel()
{
    extern __shared__ char smem[];
    uint32_t sb = smem_to_u32(smem);
    int tid = threadIdx.x;
    int wid = tid >> 5;
    int lane = tid & 31;

    int qt = blockIdx.x;          // 0..15 (128-row Q tiles)
    int bh = blockIdx.y;          // 0..63
    int q0 = qt * 128;
    size_t base = (size_t)bh * T_ * DH_;
    int nkt = 2 * qt + 2;

    // ---- Q tile cp.async ----
#pragma unroll
    for (int p = 0; p < 4; p++) {
        int idx = tid + p * 256;          // 0..1023
        int row = idx >> 3;
        int ch  = idx & 7;
        uint32_t so = SMEM_SWIZZLE_128B(row * 128 + ch * 16);
        size_t g = base + (size_t)(q0 + row) * DH_ + ch * 8;
        cp16(sb + AS_QH + so, g_qh + g);
        cp16(sb + AS_QL + so, g_ql + g);
    }
    cp_commit();

    auto load_kv = [&](int j, int s) {
        uint32_t st = sb + AS_KV + s * 32768;
#pragma unroll
        for (int p = 0; p < 2; p++) {
            int idx = tid + p * 256;      // 0..511
            int row = idx >> 3;
            int ch  = idx & 7;
            uint32_t so = SMEM_SWIZZLE_128B(row * 128 + ch * 16);
            size_t g = base + (size_t)(j * 64 + row) * DH_ + ch * 8;
            cp16(st + so,         g_kh + g);
            cp16(st + 8192 + so,  g_kl + g);
            cp16(st + 16384 + so, g_vh + g);
            cp16(st + 24576 + so, g_vl + g);
        }
        cp_commit();
    };

    load_kv(0, 0);

    uint32_t qh[4][4], ql[4][4];
    float O[8][4];
#pragma unroll
    for (int dt = 0; dt < 8; dt++)
#pragma unroll
        for (int c = 0; c < 4; c++) O[dt][c] = 0.f;
    float m0r = -1e30f, m1r = -1e30f, l0r = 0.f, l1r = 0.f;

    int g4 = lane >> 2;            // row within m16 block
    int c2 = 2 * (lane & 3);       // col pair base
    int a_row = lane & 15;
    int a_cb  = (lane >> 4) << 4;
    int b_row = lane & 7;
    int b_cb  = ((lane >> 3) & 1) << 4;
    int v_row = (lane & 7) + ((lane >> 3) & 1) * 8;

    for (int j = 0; j < nkt; j++) {
        int s = j & 1;
        if (j + 1 < nkt) {
            load_kv(j + 1, (j + 1) & 1);
            asm volatile("cp.async.wait_group 1;" ::: "memory");
        } else {
            asm volatile("cp.async.wait_group 0;" ::: "memory");
        }
        __syncthreads();

        if (j == 0) {
            // build Q fragments (once)
#pragma unroll
            for (int ks = 0; ks < 4; ks++) {
                uint32_t off = SMEM_SWIZZLE_128B((wid * 16 + a_row) * 128 + ks * 32 + a_cb);
                ldsm_x4(qh[ks], sb + AS_QH + off);
                ldsm_x4(ql[ks], sb + AS_QL + off);
            }
        }

        uint32_t stK = sb + AS_KV + s * 32768;
        uint32_t stV = stK + 16384;

        // ---- S = Q @ K^T (3-term) ----
        float S[8][4];
#pragma unroll
        for (int jt = 0; jt < 8; jt++) {
#pragma unroll
            for (int c = 0; c < 4; c++) S[jt][c] = 0.f;
#pragma unroll
            for (int ks = 0; ks < 4; ks++) {
                uint32_t off = SMEM_SWIZZLE_128B((jt * 8 + b_row) * 128 + ks * 32 + b_cb);
                uint32_t kh[2], kl[2];
                ldsm_x2(kh, stK + off);
                ldsm_x2(kl, stK + 8192 + off);
                mma_bf16(S[jt], qh[ks], kh);
                mma_bf16(S[jt], qh[ks], kl);
                mma_bf16(S[jt], ql[ks], kh);
            }
        }

        // ---- causal mask (diagonal tiles only) ----
        if (j >= 2 * qt) {
            int r0 = q0 + wid * 16 + g4;
            int cb = j * 64 + c2;
#pragma unroll
            for (int jt = 0; jt < 8; jt++) {
                int c0 = cb + jt * 8;
                if (c0 > r0)     S[jt][0] = -1e30f;
                if (c0 + 1 > r0) S[jt][1] = -1e30f;
                if (c0 > r0 + 8)     S[jt][2] = -1e30f;
                if (c0 + 1 > r0 + 8) S[jt][3] = -1e30f;
            }
        }

        // ---- online softmax ----
        float mx0 = -1e30f, mx1 = -1e30f;
#pragma unroll
        for (int jt = 0; jt < 8; jt++) {
            mx0 = fmaxf(mx0, fmaxf(S[jt][0], S[jt][1]));
            mx1 = fmaxf(mx1, fmaxf(S[jt][2], S[jt][3]));
        }
        mx0 = fmaxf(mx0, __shfl_xor_sync(0xffffffffu, mx0, 1));
        mx0 = fmaxf(mx0, __shfl_xor_sync(0xffffffffu, mx0, 2));
        mx1 = fmaxf(mx1, __shfl_xor_sync(0xffffffffu, mx1, 1));
        mx1 = fmaxf(mx1, __shfl_xor_sync(0xffffffffu, mx1, 2));

        float mn0 = fmaxf(m0r, mx0), mn1 = fmaxf(m1r, mx1);
        float al0 = __expf(m0r - mn0), al1 = __expf(m1r - mn1);
        m0r = mn0; m1r = mn1;

        float s0 = 0.f, s1 = 0.f;
#pragma unroll
        for (int jt = 0; jt < 8; jt++) {
            S[jt][0] = __expf(S[jt][0] - mn0); s0 += S[jt][0];
            S[jt][1] = __expf(S[jt][1] - mn0); s0 += S[jt][1];
            S[jt][2] = __expf(S[jt][2] - mn1); s1 += S[jt][2];
            S[jt][3] = __expf(S[jt][3] - mn1); s1 += S[jt][3];
        }
        s0 += __shfl_xor_sync(0xffffffffu, s0, 1);
        s0 += __shfl_xor_sync(0xffffffffu, s0, 2);
        s1 += __shfl_xor_sync(0xffffffffu, s1, 1);
        s1 += __shfl_xor_sync(0xffffffffu, s1, 2);
        l0r = l0r * al0 + s0;
        l1r = l1r * al1 + s1;

#pragma unroll
        for (int dt = 0; dt < 8; dt++) {
            O[dt][0] *= al0; O[dt][1] *= al0;
            O[dt][2] *= al1; O[dt][3] *= al1;
        }

        // ---- pack P hi (trunc) / lo as A-fragments ----
        uint32_t aPh[4][4], aPl[4][4];
#pragma unroll
        for (int ks2 = 0; ks2 < 4; ks2++) {
#pragma unroll
            for (int q = 0; q < 4; q++) {
                int tile = 2 * ks2 + (q >> 1);
                int cb = (q & 1) * 2;
                float p0 = S[tile][cb], p1 = S[tile][cb + 1];
                uint32_t t0 = __float_as_uint(p0) & 0xFFFF0000u;
                uint32_t t1 = __float_as_uint(p1) & 0xFFFF0000u;
                aPh[ks2][q] = (t0 >> 16) | t1;
                aPl[ks2][q] = cvt_bf16x2(p1 - __uint_as_float(t1),
                                         p0 - __uint_as_float(t0));
            }
        }

        // ---- O += P @ V (3-term) ----
#pragma unroll
        for (int dt = 0; dt < 8; dt++) {
#pragma unroll
            for (int ks2 = 0; ks2 < 4; ks2++) {
                uint32_t off = SMEM_SWIZZLE_128B((ks2 * 16 + v_row) * 128 + dt * 16);
                uint32_t vh[2], vl[2];
                ldsm_x2_trans(vh, stV + off);
                ldsm_x2_trans(vl, stV + 8192 + off);
                mma_bf16(O[dt], aPh[ks2], vh);
                mma_bf16(O[dt], aPh[ks2], vl);
                mma_bf16(O[dt], aPl[ks2], vh);
            }
        }
        __syncthreads();
    }

    // ---- epilogue: y = O / l, split bf16 hi/lo ----
    float li0 = 1.f / l0r, li1 = 1.f / l1r;
    int b = bh >> 4, h = bh & 15;
    int r0 = q0 + wid * 16 + g4;
#pragma unroll
    for (int dt = 0; dt < 8; dt++) {
        int d = dt * 8 + c2;
        {
            float v0 = O[dt][0] * li0, v1 = O[dt][1] * li0;
            size_t off = (size_t)(b * T_ + r0) * C_ + h * DH_ + d;
            __nv_bfloat16 h0 = __float2bfloat16(v0), h1 = __float2bfloat16(v1);
            float lo0 = v0 - __bfloat162float(h0), lo1 = v1 - __bfloat162float(h1);
            uint16_t u0, u1; memcpy(&u0, &h0, 2); memcpy(&u1, &h1, 2);
            *(uint32_t*)(g_yh + off) = (uint32_t)u0 | ((uint32_t)u1 << 16);
            *(uint32_t*)(g_yl + off) = cvt_bf16x2(lo1, lo0);
        }
        {
            float v0 = O[dt][2] * li1, v1 = O[dt][3] * li1;
            size_t off = (size_t)(b * T_ + r0 + 8) * C_ + h * DH_ + d;
            __nv_bfloat16 h0 = __float2bfloat16(v0), h1 = __float2bfloat16(v1);
            float lo0 = v0 - __bfloat162float(h0), lo1 = v1 - __bfloat162float(h1);
            uint16_t u0, u1; memcpy(&u0, &h0, 2); memcpy(&u1, &h1, 2);
            *(uint32_t*)(g_yh + off) = (uint32_t)u0 | ((uint32_t)u1 << 16);
            *(uint32_t*)(g_yl + off) = cvt_bf16x2(lo1, lo0);
        }
    }
}

// ---------------------------------------------------------------------------
extern "C" void kernel_launch(void* const* d_in, const int* in_sizes, int n_in,
                              void* d_out, int out_size)
{
    const float* x      = (const float*)d_in[0];
    const float* w_qkv  = (const float*)d_in[1];
    const float* w_proj = (const float*)d_in[2];
    float* out = (float*)d_out;
    (void)in_sizes; (void)n_in; (void)out_size;

    cudaFuncSetAttribute(mma_gemm_kernel,
                         cudaFuncAttributeMaxDynamicSharedMemorySize, SM_GEMM_TOTAL);
    cudaFuncSetAttribute(attn_mma_kernel,
                         cudaFuncAttributeMaxDynamicSharedMemorySize, AS_TOTAL);

    __nv_bfloat16 *xh, *xl, *yh, *yl, *wqh, *wql, *wph, *wpl;
    cudaGetSymbolAddress((void**)&xh,  g_xh);
    cudaGetSymbolAddress((void**)&xl,  g_xl);
    cudaGetSymbolAddress((void**)&yh,  g_yh);
    cudaGetSymbolAddress((void**)&yl,  g_yl);
    cudaGetSymbolAddress((void**)&wqh, g_wqkvTh);
    cudaGetSymbolAddress((void**)&wql, g_wqkvTl);
    cudaGetSymbolAddress((void**)&wph, g_wprojTh);
    cudaGetSymbolAddress((void**)&wpl, g_wprojTl);

    // prep
    convert_x_kernel<<<M_ * K_ / (256 * 4), 256>>>(x);
    transpose_w_kernel<<<dim3(N_QKV / 32, K_ / 32), dim3(32, 8)>>>(w_qkv, wqh, wql, N_QKV);
    transpose_w_kernel<<<dim3(C_ / 32, K_ / 32), dim3(32, 8)>>>(w_proj, wph, wpl, C_);

    // QKV GEMM with fused hi/lo split-scatter + q scale
    mma_gemm_kernel<<<dim3(N_QKV / 128, M_ / 128), 256, SM_GEMM_TOTAL>>>(
        xh, xl, wqh, wql, nullptr, 0);

    // tensor-core causal flash attention
    attn_mma_kernel<<<dim3(T_ / 128, B_ * H_), 256, AS_TOTAL>>>();

    // output projection GEMM
    mma_gemm_kernel<<<dim3(C_ / 128, M_ / 128), 256, SM_GEMM_TOTAL>>>(
        yh, yl, wph, wpl, out, 1);
}